// round 15
// baseline (speedup 1.0000x reference)
#include <cuda_runtime.h>
#include <cuda_fp16.h>
#include <math.h>
#include <stdint.h>

#define LQ   1024
#define BZ   8
#define DD   512
#define NH   8
#define DH   64
#define MTOT (BZ*LQ)   // 8192

// GEMM tiling: 128x128 tile, BK=64, single-term fp16, 2-buffer cp.async pipeline
#define LDSP        72                      // halfs per row (64 data + 8 pad)
#define ROWB        (LDSP*2)                // 144 bytes
#define PLANE_BYTES (128*ROWB)              // 18432
#define STG         (2*PLANE_BYTES)         // 36864 per stage (A + B planes)
#define PIPE        2
#define SMEM_PIPE   (PIPE*STG)              // 73728
#define NSTAGES     8                       // K=512 / BK=64

// ---------------- device scratch (allocation-free rule) ----------------
__device__ float g_V[BZ*LQ*DD];
__device__ float g_invn[BZ*LQ];
__device__ int   g_cnt[BZ*LQ];
__device__ int   g_idx[(size_t)BZ*LQ*LQ];
__device__ __half g_hf16[MTOT*DD];          // h fp16 (V + mask GEMMs)
__device__ __half g_Wvf16[DD*DD];           // Wv fp16

// ---------------- helpers ----------------
__device__ __forceinline__ uint32_t smem_u32(const void* p) {
    uint32_t a;
    asm("{ .reg .u64 t; cvta.to.shared.u64 t, %1; cvt.u32.u64 %0, t; }" : "=r"(a) : "l"(p));
    return a;
}
__device__ __forceinline__ void cp_async16(uint32_t dst, const void* src) {
    asm volatile("cp.async.cg.shared.global [%0], [%1], 16;" :: "r"(dst), "l"(src) : "memory");
}
__device__ __forceinline__ void ldsm_x4(uint32_t* r, uint32_t addr) {
    asm volatile("ldmatrix.sync.aligned.m8n8.x4.shared.b16 {%0,%1,%2,%3}, [%4];"
                 : "=r"(r[0]), "=r"(r[1]), "=r"(r[2]), "=r"(r[3]) : "r"(addr));
}
__device__ __forceinline__ void mma_f16(float* c, const uint32_t* a, uint32_t b0, uint32_t b1) {
    asm volatile(
        "mma.sync.aligned.m16n8k16.row.col.f32.f16.f16.f32 "
        "{%0,%1,%2,%3}, {%4,%5,%6,%7}, {%8,%9}, {%0,%1,%2,%3};"
        : "+f"(c[0]), "+f"(c[1]), "+f"(c[2]), "+f"(c[3])
        : "r"(a[0]), "r"(a[1]), "r"(a[2]), "r"(a[3]), "r"(b0), "r"(b1));
}

// ---------------------------------------------------------------------------
// Kernel 1: fused norms + counter init + h->fp16 + Wv->fp16
// blocks 0..1023: h rows (warp per row). blocks 1024..1279: Wv conversion.
// ---------------------------------------------------------------------------
__global__ void __launch_bounds__(256) prep_kernel(
    const float* __restrict__ query, const float* __restrict__ Wv)
{
    int bx = blockIdx.x, tid = threadIdx.x;
    if (bx < 1024) {
        int wid = tid >> 5, lane = tid & 31;
        int m = bx * 8 + wid;
        int b = m >> 10, i = m & 1023;
        if (tid < 8) g_cnt[bx * 8 + tid] = 0;
        const float4* p = (const float4*)(query + (size_t)i*(BZ*DD) + (size_t)b*DD);
        __half2* d = (__half2*)(g_hf16 + (size_t)m * DD);
        float ss = 0.f;
        #pragma unroll
        for (int j = 0; j < 4; ++j) {
            float4 v = p[lane + j*32];
            ss += v.x*v.x + v.y*v.y + v.z*v.z + v.w*v.w;
            d[(lane + j*32)*2 + 0] = __floats2half2_rn(v.x, v.y);
            d[(lane + j*32)*2 + 1] = __floats2half2_rn(v.z, v.w);
        }
        #pragma unroll
        for (int o = 16; o > 0; o >>= 1) ss += __shfl_xor_sync(0xffffffffu, ss, o);
        if (lane == 0) g_invn[m] = 1.f / fmaxf(sqrtf(ss), 1e-8f);
    } else {
        int e = (bx - 1024) * 256 + tid;          // 0..65535 float4s
        float4 v = *(const float4*)(Wv + (size_t)e * 4);
        __half2* d = (__half2*)(g_Wvf16 + (size_t)e * 4);
        d[0] = __floats2half2_rn(v.x, v.y);
        d[1] = __floats2half2_rn(v.z, v.w);
    }
}

// ---------------------------------------------------------------------------
// fp16 HMMA mainloop: acc[2][8][4] += A[128xK] * B[128xK]^T, K=512.
// 8 warps (4Mx2N), warp tile 32x64, BK=64, 2-buffer pipeline.
// ---------------------------------------------------------------------------
__device__ __forceinline__ void hmma_loop(char* smem,
    const __half* __restrict__ A, const __half* __restrict__ B, float acc[2][8][4])
{
    const __half* gsrc[2] = { A, B };
    int tid = threadIdx.x, lane = tid & 31, wid = tid >> 5;
    int warp_m = wid & 3, warp_n = wid >> 2;
    uint32_t sbase = smem_u32(smem);

    int cpl[8], crow[8], cch[8];
    #pragma unroll
    for (int it = 0; it < 8; ++it) {
        int c = tid + it * 256;
        cpl[it]  = c >> 10;
        int idx  = c & 1023;
        crow[it] = idx >> 3;
        cch[it]  = idx & 7;
    }

    int r8 = lane & 7, g = lane >> 3;
    uint32_t aoff[2];
    #pragma unroll
    for (int mf = 0; mf < 2; ++mf)
        aoff[mf] = (warp_m*32 + mf*16 + r8 + (g & 1)*8) * ROWB + ((g >> 1) & 1)*16;
    int jsel = (lane >> 4) & 1, ksel = (lane >> 3) & 1;
    uint32_t boff[4];
    #pragma unroll
    for (int jp = 0; jp < 4; ++jp)
        boff[jp] = (warp_n*64 + jp*16 + jsel*8 + r8) * ROWB + ksel*16;

    #pragma unroll
    for (int it = 0; it < 8; ++it) {
        uint32_t dst = sbase + cpl[it]*PLANE_BYTES + crow[it]*ROWB + cch[it]*16;
        cp_async16(dst, gsrc[cpl[it]] + (size_t)crow[it]*DD + cch[it]*8);
    }
    asm volatile("cp.async.commit_group;" ::: "memory");

    for (int s = 0; s < NSTAGES; ++s) {
        asm volatile("cp.async.wait_group 0;" ::: "memory");
        __syncthreads();
        if (s + 1 < NSTAGES) {
            int k0 = (s + 1) * 64;
            uint32_t dbase = sbase + ((s + 1) & 1) * STG;
            #pragma unroll
            for (int it = 0; it < 8; ++it) {
                uint32_t dst = dbase + cpl[it]*PLANE_BYTES + crow[it]*ROWB + cch[it]*16;
                cp_async16(dst, gsrc[cpl[it]] + (size_t)crow[it]*DD + k0 + cch[it]*8);
            }
            asm volatile("cp.async.commit_group;" ::: "memory");
        }

        uint32_t st = sbase + (s & 1) * STG;
        #pragma unroll
        for (int ks = 0; ks < 4; ++ks) {
            uint32_t kofs = ks * 32;
            uint32_t ah[2][4];
            #pragma unroll
            for (int mf = 0; mf < 2; ++mf)
                ldsm_x4(ah[mf], st + aoff[mf] + kofs);
            uint32_t bb[4][4];
            #pragma unroll
            for (int jp = 0; jp < 4; ++jp)
                ldsm_x4(bb[jp], st + PLANE_BYTES + boff[jp] + kofs);
            #pragma unroll
            for (int jp = 0; jp < 4; ++jp)
                #pragma unroll
                for (int hf = 0; hf < 2; ++hf)
                    #pragma unroll
                    for (int mf = 0; mf < 2; ++mf)
                        mma_f16(acc[mf][jp*2+hf], ah[mf], bb[jp][hf*2], bb[jp][hf*2+1]);
        }
    }
}

// ---------------------------------------------------------------------------
// Kernel 2: fused GEMM launch.
//  blocks [0,256):   V projection tiles
//  blocks [256,544): mask cos tiles (upper-triangular pairs + mirror)
// ---------------------------------------------------------------------------
__global__ void __launch_bounds__(256, 2) fused_gemm_kernel(
    const float* __restrict__ query, const float* __restrict__ segments,
    const float* __restrict__ bv)
{
    extern __shared__ char dynsmem[];
    int bx = blockIdx.x;
    int lane = threadIdx.x & 31, wid = threadIdx.x >> 5;
    int warp_m = wid & 3, warp_n = wid >> 2;

    float acc[2][8][4];
    #pragma unroll
    for (int a = 0; a < 2; ++a)
        #pragma unroll
        for (int b = 0; b < 8; ++b)
            #pragma unroll
            for (int c = 0; c < 4; ++c) acc[a][b][c] = 0.f;

    if (bx < 256) {
        // ---------------- V tile ----------------
        int n0 = (bx & 3) * 128, m0 = (bx >> 2) * 128;

        hmma_loop(dynsmem,
            g_hf16 + (size_t)m0 * DD,
            g_Wvf16 + (size_t)n0 * DD, acc);

        int row0 = m0 + warp_m*32 + (lane >> 2);
        int col0 = n0 + warp_n*64 + (lane & 3)*2;
        #pragma unroll
        for (int mf = 0; mf < 2; ++mf) {
            #pragma unroll
            for (int jf = 0; jf < 8; ++jf) {
                int cc = col0 + jf*8;
                float2 b2 = *(const float2*)(bv + cc);
                float2 o0, o1;
                o0.x = acc[mf][jf][0] + b2.x; o0.y = acc[mf][jf][1] + b2.y;
                o1.x = acc[mf][jf][2] + b2.x; o1.y = acc[mf][jf][3] + b2.y;
                *(float2*)(g_V + (size_t)(row0 + mf*16    )*DD + cc) = o0;
                *(float2*)(g_V + (size_t)(row0 + mf*16 + 8)*DD + cc) = o1;
            }
        }
    } else {
        // ---------------- mask tile ----------------
        int e = bx - 256;
        int b = e / 36;
        int t = e % 36, bi = 0;
        while (t >= 8 - bi) { t -= 8 - bi; ++bi; }
        int bj = bi + t;
        int i0 = bi * 128, j0 = bj * 128;
        bool mirror = (bi != bj);

        hmma_loop(dynsmem,
            g_hf16 + (size_t)(b*LQ + i0) * DD,
            g_hf16 + (size_t)(b*LQ + j0) * DD, acc);

        const float* seg = segments + (size_t)b * LQ * 2;
        int   gi[4], rid[4];
        float ni[4], si[4], ei[4], li[4];
        #pragma unroll
        for (int u = 0; u < 4; ++u) {
            int r = i0 + warp_m*32 + (lane >> 2) + (u >> 1)*16 + (u & 1)*8;
            gi[u] = r; rid[u] = b*LQ + r;
            ni[u] = g_invn[rid[u]];
            float cc = seg[r*2], ll = seg[r*2+1];
            si[u] = cc - ll*0.5f; ei[u] = cc + ll*0.5f; li[u] = ll;
        }

        #pragma unroll
        for (int jf = 0; jf < 8; ++jf) {
            #pragma unroll
            for (int c2 = 0; c2 < 2; ++c2) {
                int gj = j0 + warp_n*64 + jf*8 + (lane & 3)*2 + c2;
                float nj = g_invn[b*LQ + gj];
                float cj = seg[gj*2], lj = seg[gj*2+1];
                float sj = cj - lj*0.5f, ej = cj + lj*0.5f;
                #pragma unroll
                for (int u = 0; u < 4; ++u) {
                    float cosv = acc[u >> 1][jf][(u & 1)*2 + c2] * ni[u] * nj;
                    if (fabsf(cosv - 0.2f) < 2e-3f) {
                        // exact fp32 recheck (rare)
                        const float* hp = query + (size_t)gi[u]*(BZ*DD) + (size_t)b*DD;
                        const float* hq = query + (size_t)gj   *(BZ*DD) + (size_t)b*DD;
                        float d = 0.f;
                        for (int k = 0; k < DD; ++k) d += hp[k] * hq[k];
                        cosv = d * ni[u] * nj;
                    }
                    float inter = fmaxf(fminf(ei[u], ej) - fmaxf(si[u], sj), 0.f);
                    float uni   = (li[u] + lj) - inter;
                    float iou   = inter / uni;
                    bool valid = ((iou <= 0.2f) || (gi[u] == gj)) && (cosv > 0.2f);
                    if (valid) {
                        int p = atomicAdd(&g_cnt[rid[u]], 1);
                        g_idx[((size_t)rid[u] << 10) + p] = gj;
                        if (mirror) {
                            int rj = b*LQ + gj;
                            int p2 = atomicAdd(&g_cnt[rj], 1);
                            g_idx[((size_t)rj << 10) + p2] = gi[u];
                        }
                    }
                }
            }
        }
    }
}

// ---------------------------------------------------------------------------
// Kernel 3: sparse attention + residual. 4 rows per block.
// c==1 (norm): out = V[j] + h  (softmax weight is exactly 1).
// c>=2 (rare): compute Q_i, K_j on the fly in EXACT fp32 from query/Wq/Wk,
// per-head scores + softmax + gather V.
// ---------------------------------------------------------------------------
__global__ void __launch_bounds__(256) sattn_kernel(
    const float* __restrict__ query,
    const float* __restrict__ Wq, const float* __restrict__ bq,
    const float* __restrict__ Wk, const float* __restrict__ bk,
    float* __restrict__ out)
{
    __shared__ float hs[DD];        // h_i
    __shared__ float qs[DD];        // Q_i row
    __shared__ float hjs[DD];       // h_j
    __shared__ float ks[DD];        // K_j row
    __shared__ float sc[NH][LQ];    // scores (worst case)

    int tid = threadIdx.x;
    int h = tid >> 5, lane = tid & 31;

    for (int r4 = 0; r4 < 4; ++r4) {
        int row = blockIdx.x * 4 + r4;
        int b = row >> 10, i = row & 1023;
        int c = g_cnt[row];
        const int* idx = g_idx + ((size_t)row << 10);
        size_t hoff = (size_t)i*(BZ*DD) + (size_t)b*DD;

        if (c == 1) {
            int j = idx[0];
            const float* Vr = g_V + (size_t)(b*LQ + j) * DD;
            float2 v = *(const float2*)(Vr + tid*2);
            float2 r = *(const float2*)(query + hoff + tid*2);
            float2 o; o.x = v.x + r.x; o.y = v.y + r.y;
            *(float2*)(out + hoff + tid*2) = o;
            continue;
        }

        // ---- rare heavy path: exact fp32 scores ----
        *(float2*)&hs[tid*2] = *(const float2*)(query + hoff + tid*2);
        __syncthreads();
        // Q_i: each thread 2 output cols
        #pragma unroll
        for (int q = 0; q < 2; ++q) {
            int n = tid*2 + q;
            const float* wr = Wq + (size_t)n * DD;
            float s = 0.f;
            for (int k = 0; k < DD; ++k) s += hs[k] * wr[k];
            qs[n] = s + bq[n];
        }
        __syncthreads();

        for (int t = 0; t < c; ++t) {
            int j = idx[t];
            *(float2*)&hjs[tid*2] = *(const float2*)(query + (size_t)j*(BZ*DD) + (size_t)b*DD + tid*2);
            __syncthreads();
            #pragma unroll
            for (int q = 0; q < 2; ++q) {
                int n = tid*2 + q;
                const float* wr = Wk + (size_t)n * DD;
                float s = 0.f;
                for (int k = 0; k < DD; ++k) s += hjs[k] * wr[k];
                ks[n] = s + bk[n];
            }
            __syncthreads();
            // per-head score: warp h over 64 dims (2 per lane)
            int d0 = h*DH + lane*2;
            float s = qs[d0]*ks[d0] + qs[d0+1]*ks[d0+1];
            #pragma unroll
            for (int o = 16; o > 0; o >>= 1) s += __shfl_xor_sync(0xffffffffu, s, o);
            if (lane == 0) sc[h][t] = s * 0.125f;
            __syncthreads();
        }

        // softmax per head (warp h)
        float m = -1e30f;
        for (int t = lane; t < c; t += 32) m = fmaxf(m, sc[h][t]);
        #pragma unroll
        for (int o = 16; o > 0; o >>= 1) m = fmaxf(m, __shfl_xor_sync(0xffffffffu, m, o));
        float l = 0.f;
        for (int t = lane; t < c; t += 32) {
            float p = expf(sc[h][t] - m);
            sc[h][t] = p;
            l += p;
        }
        #pragma unroll
        for (int o = 16; o > 0; o >>= 1) l += __shfl_xor_sync(0xffffffffu, l, o);
        __syncwarp();

        // gather V: thread owns dims d0, d0+1
        int d0 = h*DH + lane*2;
        float o0 = 0.f, o1 = 0.f;
        for (int t = 0; t < c; ++t) {
            int j = idx[t];
            float p = sc[h][t];
            const float* Vr = g_V + (size_t)(b*LQ + j) * DD;
            float2 v = *(const float2*)(Vr + d0);
            o0 += p * v.x;
            o1 += p * v.y;
        }
        float invl = 1.f / l;
        float2 ov;
        ov.x = o0*invl + hs[d0];
        ov.y = o1*invl + hs[d0+1];
        *(float2*)(out + hoff + d0) = ov;
        __syncthreads();
    }
}

// ---------------------------------------------------------------------------
extern "C" void kernel_launch(void* const* d_in, const int* in_sizes, int n_in,
                              void* d_out, int out_size)
{
    const float* query    = (const float*)d_in[0];
    const float* segments = (const float*)d_in[1];
    const float* Wq = (const float*)d_in[2];
    const float* bq = (const float*)d_in[3];
    const float* Wk = (const float*)d_in[4];
    const float* bk = (const float*)d_in[5];
    const float* Wv = (const float*)d_in[6];
    const float* bv = (const float*)d_in[7];
    float* out = (float*)d_out;

    cudaFuncSetAttribute(fused_gemm_kernel, cudaFuncAttributeMaxDynamicSharedMemorySize, SMEM_PIPE);

    prep_kernel      <<<1280, 256>>>(query, Wv);
    fused_gemm_kernel<<<544, 256, SMEM_PIPE>>>(query, segments, bv);
    sattn_kernel     <<<MTOT/4, 256>>>(query, Wq, bq, Wk, bk, out);
}

// round 16
// speedup vs baseline: 2.5578x; 2.5578x over previous
#include <cuda_runtime.h>
#include <cuda_fp16.h>
#include <math.h>
#include <stdint.h>

#define LQ   1024
#define BZ   8
#define DD   512
#define NH   8
#define DH   64
#define MTOT (BZ*LQ)   // 8192

// GEMM tiling: 128x128 tile, BK=64, single-term fp16, 2-buffer cp.async pipeline
#define LDSP        72                      // halfs per row (64 data + 8 pad)
#define ROWB        (LDSP*2)                // 144 bytes
#define PLANE_BYTES (128*ROWB)              // 18432
#define STG         (2*PLANE_BYTES)         // 36864 per stage (A + B planes)
#define PIPE        2
#define SMEM_PIPE   (PIPE*STG)              // 73728
#define NSTAGES     8                       // K=512 / BK=64

// ---------------- device scratch (allocation-free rule) ----------------
__device__ float g_V[BZ*LQ*DD];
__device__ float g_invn[BZ*LQ];
__device__ int   g_cnt[BZ*LQ];
__device__ int   g_idx[(size_t)BZ*LQ*LQ];
__device__ __half g_hf16[MTOT*DD];          // h fp16 (V + mask GEMMs)
__device__ __half g_Wvf16[DD*DD];           // Wv fp16

// ---------------- helpers ----------------
__device__ __forceinline__ uint32_t smem_u32(const void* p) {
    uint32_t a;
    asm("{ .reg .u64 t; cvta.to.shared.u64 t, %1; cvt.u32.u64 %0, t; }" : "=r"(a) : "l"(p));
    return a;
}
__device__ __forceinline__ void cp_async16(uint32_t dst, const void* src) {
    asm volatile("cp.async.cg.shared.global [%0], [%1], 16;" :: "r"(dst), "l"(src) : "memory");
}
__device__ __forceinline__ void ldsm_x4(uint32_t* r, uint32_t addr) {
    asm volatile("ldmatrix.sync.aligned.m8n8.x4.shared.b16 {%0,%1,%2,%3}, [%4];"
                 : "=r"(r[0]), "=r"(r[1]), "=r"(r[2]), "=r"(r[3]) : "r"(addr));
}
__device__ __forceinline__ void mma_f16(float* c, const uint32_t* a, uint32_t b0, uint32_t b1) {
    asm volatile(
        "mma.sync.aligned.m16n8k16.row.col.f32.f16.f16.f32 "
        "{%0,%1,%2,%3}, {%4,%5,%6,%7}, {%8,%9}, {%0,%1,%2,%3};"
        : "+f"(c[0]), "+f"(c[1]), "+f"(c[2]), "+f"(c[3])
        : "r"(a[0]), "r"(a[1]), "r"(a[2]), "r"(a[3]), "r"(b0), "r"(b1));
}

// ---------------------------------------------------------------------------
// Kernel 1: fused norms + counter init + h->fp16 + Wv->fp16
// ---------------------------------------------------------------------------
__global__ void __launch_bounds__(256) prep_kernel(
    const float* __restrict__ query, const float* __restrict__ Wv)
{
    int bx = blockIdx.x, tid = threadIdx.x;
    if (bx < 1024) {
        int wid = tid >> 5, lane = tid & 31;
        int m = bx * 8 + wid;
        int b = m >> 10, i = m & 1023;
        if (tid < 8) g_cnt[bx * 8 + tid] = 0;
        const float4* p = (const float4*)(query + (size_t)i*(BZ*DD) + (size_t)b*DD);
        __half2* d = (__half2*)(g_hf16 + (size_t)m * DD);
        float ss = 0.f;
        #pragma unroll
        for (int j = 0; j < 4; ++j) {
            float4 v = p[lane + j*32];
            ss += v.x*v.x + v.y*v.y + v.z*v.z + v.w*v.w;
            d[(lane + j*32)*2 + 0] = __floats2half2_rn(v.x, v.y);
            d[(lane + j*32)*2 + 1] = __floats2half2_rn(v.z, v.w);
        }
        #pragma unroll
        for (int o = 16; o > 0; o >>= 1) ss += __shfl_xor_sync(0xffffffffu, ss, o);
        if (lane == 0) g_invn[m] = 1.f / fmaxf(sqrtf(ss), 1e-8f);
    } else {
        int e = (bx - 1024) * 256 + tid;          // 0..65535 float4s
        float4 v = *(const float4*)(Wv + (size_t)e * 4);
        __half2* d = (__half2*)(g_Wvf16 + (size_t)e * 4);
        d[0] = __floats2half2_rn(v.x, v.y);
        d[1] = __floats2half2_rn(v.z, v.w);
    }
}

// ---------------------------------------------------------------------------
// fp16 HMMA mainloop: acc[2][8][4] += A[128xK] * B[128xK]^T, K=512.
// ---------------------------------------------------------------------------
__device__ __forceinline__ void hmma_loop(char* smem,
    const __half* __restrict__ A, const __half* __restrict__ B, float acc[2][8][4])
{
    const __half* gsrc[2] = { A, B };
    int tid = threadIdx.x, lane = tid & 31, wid = tid >> 5;
    int warp_m = wid & 3, warp_n = wid >> 2;
    uint32_t sbase = smem_u32(smem);

    int cpl[8], crow[8], cch[8];
    #pragma unroll
    for (int it = 0; it < 8; ++it) {
        int c = tid + it * 256;
        cpl[it]  = c >> 10;
        int idx  = c & 1023;
        crow[it] = idx >> 3;
        cch[it]  = idx & 7;
    }

    int r8 = lane & 7, g = lane >> 3;
    uint32_t aoff[2];
    #pragma unroll
    for (int mf = 0; mf < 2; ++mf)
        aoff[mf] = (warp_m*32 + mf*16 + r8 + (g & 1)*8) * ROWB + ((g >> 1) & 1)*16;
    int jsel = (lane >> 4) & 1, ksel = (lane >> 3) & 1;
    uint32_t boff[4];
    #pragma unroll
    for (int jp = 0; jp < 4; ++jp)
        boff[jp] = (warp_n*64 + jp*16 + jsel*8 + r8) * ROWB + ksel*16;

    #pragma unroll
    for (int it = 0; it < 8; ++it) {
        uint32_t dst = sbase + cpl[it]*PLANE_BYTES + crow[it]*ROWB + cch[it]*16;
        cp_async16(dst, gsrc[cpl[it]] + (size_t)crow[it]*DD + cch[it]*8);
    }
    asm volatile("cp.async.commit_group;" ::: "memory");

    for (int s = 0; s < NSTAGES; ++s) {
        asm volatile("cp.async.wait_group 0;" ::: "memory");
        __syncthreads();
        if (s + 1 < NSTAGES) {
            int k0 = (s + 1) * 64;
            uint32_t dbase = sbase + ((s + 1) & 1) * STG;
            #pragma unroll
            for (int it = 0; it < 8; ++it) {
                uint32_t dst = dbase + cpl[it]*PLANE_BYTES + crow[it]*ROWB + cch[it]*16;
                cp_async16(dst, gsrc[cpl[it]] + (size_t)crow[it]*DD + k0 + cch[it]*8);
            }
            asm volatile("cp.async.commit_group;" ::: "memory");
        }

        uint32_t st = sbase + (s & 1) * STG;
        #pragma unroll
        for (int ks = 0; ks < 4; ++ks) {
            uint32_t kofs = ks * 32;
            uint32_t ah[2][4];
            #pragma unroll
            for (int mf = 0; mf < 2; ++mf)
                ldsm_x4(ah[mf], st + aoff[mf] + kofs);
            uint32_t bb[4][4];
            #pragma unroll
            for (int jp = 0; jp < 4; ++jp)
                ldsm_x4(bb[jp], st + PLANE_BYTES + boff[jp] + kofs);
            #pragma unroll
            for (int jp = 0; jp < 4; ++jp)
                #pragma unroll
                for (int hf = 0; hf < 2; ++hf)
                    #pragma unroll
                    for (int mf = 0; mf < 2; ++mf)
                        mma_f16(acc[mf][jp*2+hf], ah[mf], bb[jp][hf*2], bb[jp][hf*2+1]);
        }
    }
}

// ---------------------------------------------------------------------------
// Kernel 2: fused GEMM launch.
//  blocks [0,256):   V projection tiles
//  blocks [256,544): mask cos tiles (upper-triangular pairs + mirror)
// ---------------------------------------------------------------------------
__global__ void __launch_bounds__(256, 2) fused_gemm_kernel(
    const float* __restrict__ query, const float* __restrict__ segments,
    const float* __restrict__ bv)
{
    extern __shared__ char dynsmem[];
    int bx = blockIdx.x;
    int lane = threadIdx.x & 31, wid = threadIdx.x >> 5;
    int warp_m = wid & 3, warp_n = wid >> 2;

    float acc[2][8][4];
    #pragma unroll
    for (int a = 0; a < 2; ++a)
        #pragma unroll
        for (int b = 0; b < 8; ++b)
            #pragma unroll
            for (int c = 0; c < 4; ++c) acc[a][b][c] = 0.f;

    if (bx < 256) {
        // ---------------- V tile ----------------
        int n0 = (bx & 3) * 128, m0 = (bx >> 2) * 128;

        hmma_loop(dynsmem,
            g_hf16 + (size_t)m0 * DD,
            g_Wvf16 + (size_t)n0 * DD, acc);

        int row0 = m0 + warp_m*32 + (lane >> 2);
        int col0 = n0 + warp_n*64 + (lane & 3)*2;
        #pragma unroll
        for (int mf = 0; mf < 2; ++mf) {
            #pragma unroll
            for (int jf = 0; jf < 8; ++jf) {
                int cc = col0 + jf*8;
                float2 b2 = *(const float2*)(bv + cc);
                float2 o0, o1;
                o0.x = acc[mf][jf][0] + b2.x; o0.y = acc[mf][jf][1] + b2.y;
                o1.x = acc[mf][jf][2] + b2.x; o1.y = acc[mf][jf][3] + b2.y;
                *(float2*)(g_V + (size_t)(row0 + mf*16    )*DD + cc) = o0;
                *(float2*)(g_V + (size_t)(row0 + mf*16 + 8)*DD + cc) = o1;
            }
        }
    } else {
        // ---------------- mask tile ----------------
        int e = bx - 256;
        int b = e / 36;
        int t = e % 36, bi = 0;
        while (t >= 8 - bi) { t -= 8 - bi; ++bi; }
        int bj = bi + t;
        int i0 = bi * 128, j0 = bj * 128;
        bool mirror = (bi != bj);

        hmma_loop(dynsmem,
            g_hf16 + (size_t)(b*LQ + i0) * DD,
            g_hf16 + (size_t)(b*LQ + j0) * DD, acc);

        const float* seg = segments + (size_t)b * LQ * 2;
        int   gi[4], rid[4];
        float ni[4], si[4], ei[4], li[4];
        #pragma unroll
        for (int u = 0; u < 4; ++u) {
            int r = i0 + warp_m*32 + (lane >> 2) + (u >> 1)*16 + (u & 1)*8;
            gi[u] = r; rid[u] = b*LQ + r;
            ni[u] = g_invn[rid[u]];
            float cc = seg[r*2], ll = seg[r*2+1];
            si[u] = cc - ll*0.5f; ei[u] = cc + ll*0.5f; li[u] = ll;
        }

        #pragma unroll
        for (int jf = 0; jf < 8; ++jf) {
            #pragma unroll
            for (int c2 = 0; c2 < 2; ++c2) {
                int gj = j0 + warp_n*64 + jf*8 + (lane & 3)*2 + c2;
                float nj = g_invn[b*LQ + gj];
                float cj = seg[gj*2], lj = seg[gj*2+1];
                float sj = cj - lj*0.5f, ej = cj + lj*0.5f;
                #pragma unroll
                for (int u = 0; u < 4; ++u) {
                    float cosv = acc[u >> 1][jf][(u & 1)*2 + c2] * ni[u] * nj;
                    if (fabsf(cosv - 0.2f) < 2e-3f) {
                        // exact fp32 recheck (rare)
                        const float* hp = query + (size_t)gi[u]*(BZ*DD) + (size_t)b*DD;
                        const float* hq = query + (size_t)gj   *(BZ*DD) + (size_t)b*DD;
                        float d = 0.f;
                        for (int k = 0; k < DD; ++k) d += hp[k] * hq[k];
                        cosv = d * ni[u] * nj;
                    }
                    float inter = fmaxf(fminf(ei[u], ej) - fmaxf(si[u], sj), 0.f);
                    float uni   = (li[u] + lj) - inter;
                    float iou   = inter / uni;
                    bool valid = ((iou <= 0.2f) || (gi[u] == gj)) && (cosv > 0.2f);
                    if (valid) {
                        int p = atomicAdd(&g_cnt[rid[u]], 1);
                        g_idx[((size_t)rid[u] << 10) + p] = gj;
                        if (mirror) {
                            int rj = b*LQ + gj;
                            int p2 = atomicAdd(&g_cnt[rj], 1);
                            g_idx[((size_t)rj << 10) + p2] = gi[u];
                        }
                    }
                }
            }
        }
    }
}

// ---------------------------------------------------------------------------
// Kernel 3: sparse attention + residual. 4 rows per block.
// c==1 (norm): out = V[j] + h  (softmax weight is exactly 1).
// c>=2 (rare): exact fp32 Q_i/K_j computed on the fly with WARP-COALESCED
// W reads (warp owns 64 output cols; lanes read W[n, lane+32j] contiguously,
// shuffle-reduce) — fixes the R15 32-sector-per-LDG catastrophe.
// ---------------------------------------------------------------------------
__global__ void __launch_bounds__(256) sattn_kernel(
    const float* __restrict__ query,
    const float* __restrict__ Wq, const float* __restrict__ bq,
    const float* __restrict__ Wk, const float* __restrict__ bk,
    float* __restrict__ out)
{
    __shared__ float hs[DD];        // h_i
    __shared__ float qs[DD];        // Q_i row
    __shared__ float hjs[DD];       // h_j
    __shared__ float ks[DD];        // K_j row
    __shared__ float sc[NH][LQ];    // scores (worst case)

    int tid = threadIdx.x;
    int wid = tid >> 5, lane = tid & 31;

    for (int r4 = 0; r4 < 4; ++r4) {
        int row = blockIdx.x * 4 + r4;
        int b = row >> 10, i = row & 1023;
        int c = g_cnt[row];
        const int* idx = g_idx + ((size_t)row << 10);
        size_t hoff = (size_t)i*(BZ*DD) + (size_t)b*DD;

        if (c == 1) {
            int j = idx[0];
            const float* Vr = g_V + (size_t)(b*LQ + j) * DD;
            float2 v = *(const float2*)(Vr + tid*2);
            float2 r = *(const float2*)(query + hoff + tid*2);
            float2 o; o.x = v.x + r.x; o.y = v.y + r.y;
            *(float2*)(out + hoff + tid*2) = o;
            continue;
        }

        // ---- rare heavy path: exact fp32 scores, coalesced W reads ----
        *(float2*)&hs[tid*2] = *(const float2*)(query + hoff + tid*2);
        __syncthreads();
        // Q_i: warp wid computes output cols [wid*64, wid*64+64)
        for (int nn = 0; nn < 64; ++nn) {
            int n = wid*64 + nn;
            const float* wr = Wq + (size_t)n * DD;
            float s = 0.f;
            #pragma unroll
            for (int j = 0; j < 16; ++j) s += hs[lane + j*32] * wr[lane + j*32];
            #pragma unroll
            for (int o = 16; o > 0; o >>= 1) s += __shfl_xor_sync(0xffffffffu, s, o);
            if (lane == 0) qs[n] = s + bq[n];
        }
        __syncthreads();

        for (int t = 0; t < c; ++t) {
            int j = idx[t];
            *(float2*)&hjs[tid*2] = *(const float2*)(query + (size_t)j*(BZ*DD) + (size_t)b*DD + tid*2);
            __syncthreads();
            // K_j: warp-coalesced
            for (int nn = 0; nn < 64; ++nn) {
                int n = wid*64 + nn;
                const float* wr = Wk + (size_t)n * DD;
                float s = 0.f;
                #pragma unroll
                for (int jj = 0; jj < 16; ++jj) s += hjs[lane + jj*32] * wr[lane + jj*32];
                #pragma unroll
                for (int o = 16; o > 0; o >>= 1) s += __shfl_xor_sync(0xffffffffu, s, o);
                if (lane == 0) ks[n] = s + bk[n];
            }
            __syncthreads();
            // per-head score: warp h over 64 dims (2 per lane)
            int d0 = wid*DH + lane*2;
            float s = qs[d0]*ks[d0] + qs[d0+1]*ks[d0+1];
            #pragma unroll
            for (int o = 16; o > 0; o >>= 1) s += __shfl_xor_sync(0xffffffffu, s, o);
            if (lane == 0) sc[wid][t] = s * 0.125f;
            __syncthreads();
        }

        // softmax per head (warp wid = head)
        float m = -1e30f;
        for (int t = lane; t < c; t += 32) m = fmaxf(m, sc[wid][t]);
        #pragma unroll
        for (int o = 16; o > 0; o >>= 1) m = fmaxf(m, __shfl_xor_sync(0xffffffffu, m, o));
        float l = 0.f;
        for (int t = lane; t < c; t += 32) {
            float p = expf(sc[wid][t] - m);
            sc[wid][t] = p;
            l += p;
        }
        #pragma unroll
        for (int o = 16; o > 0; o >>= 1) l += __shfl_xor_sync(0xffffffffu, l, o);
        __syncwarp();

        // gather V: thread owns dims d0, d0+1
        int d0 = wid*DH + lane*2;
        float o0 = 0.f, o1 = 0.f;
        for (int t = 0; t < c; ++t) {
            int j = idx[t];
            float p = sc[wid][t];
            const float* Vr = g_V + (size_t)(b*LQ + j) * DD;
            float2 v = *(const float2*)(Vr + d0);
            o0 += p * v.x;
            o1 += p * v.y;
        }
        float invl = 1.f / l;
        float2 ov;
        ov.x = o0*invl + hs[d0];
        ov.y = o1*invl + hs[d0+1];
        *(float2*)(out + hoff + d0) = ov;
        __syncthreads();
    }
}

// ---------------------------------------------------------------------------
extern "C" void kernel_launch(void* const* d_in, const int* in_sizes, int n_in,
                              void* d_out, int out_size)
{
    const float* query    = (const float*)d_in[0];
    const float* segments = (const float*)d_in[1];
    const float* Wq = (const float*)d_in[2];
    const float* bq = (const float*)d_in[3];
    const float* Wk = (const float*)d_in[4];
    const float* bk = (const float*)d_in[5];
    const float* Wv = (const float*)d_in[6];
    const float* bv = (const float*)d_in[7];
    float* out = (float*)d_out;

    cudaFuncSetAttribute(fused_gemm_kernel, cudaFuncAttributeMaxDynamicSharedMemorySize, SMEM_PIPE);

    prep_kernel      <<<1280, 256>>>(query, Wv);
    fused_gemm_kernel<<<544, 256, SMEM_PIPE>>>(query, segments, bv);
    sattn_kernel     <<<MTOT/4, 256>>>(query, Wq, bq, Wk, bk, out);
}